// round 1
// baseline (speedup 1.0000x reference)
#include <cuda_runtime.h>
#include <cstdint>

// ---------------------------------------------------------------------------
// ButterFlyNet2D forward, fully fused per level.
// Layout convention for activations: [B][Nblocks][C=16][S][S], which for the
// first level coincides with NCHW [B][64][32][32].
// ---------------------------------------------------------------------------

#define BATCH 256

__device__ float g_bufA[BATCH * 64 * 32 * 32]; // 16,777,216 floats (64 MB)
__device__ float g_bufB[BATCH * 64 * 32 * 32];

// ---- packed f32x2 helpers (Blackwell FFMA2 path) --------------------------
typedef unsigned long long f2_t;

__device__ __forceinline__ f2_t pk2(float a, float b) {
    f2_t r;
    asm("mov.b64 %0, {%1, %2};" : "=l"(r)
        : "r"(__float_as_uint(a)), "r"(__float_as_uint(b)));
    return r;
}
__device__ __forceinline__ void upk2(f2_t v, float& a, float& b) {
    unsigned lo, hi;
    asm("mov.b64 {%0, %1}, %2;" : "=r"(lo), "=r"(hi) : "l"(v));
    a = __uint_as_float(lo);
    b = __uint_as_float(hi);
}
__device__ __forceinline__ f2_t fma2(f2_t a, f2_t b, f2_t c) {
    f2_t d;
    asm("fma.rn.f32x2 %0, %1, %2, %3;" : "=l"(d) : "l"(a), "l"(b), "l"(c));
    return d;
}

// ---------------------------------------------------------------------------
// Layer 0: x[B,1,64,64] -> split(relu(x),relu(-x),0,0) -> conv2x2(4->64)
//          -> +b0 -> relu -> wrap-pad -> avgpool2   => out[B,64,32,32]
// ---------------------------------------------------------------------------
__global__ __launch_bounds__(256)
void k_layer0(const float* __restrict__ x, const float* __restrict__ W0,
              const float* __restrict__ b0, float* __restrict__ out)
{
    __shared__ float ws[512]; // [oc][ic(0..1)][kh][kw]
    __shared__ float bs[64];
    const int tid = threadIdx.x;
    for (int t = tid; t < 512; t += 256) {
        int oc = t >> 3, r = t & 7; // r = ic*4 + kh*2 + kw, ic < 2
        ws[t] = W0[oc * 16 + r];
    }
    if (tid < 64) bs[tid] = b0[tid];
    __syncthreads();

    const int pos = blockIdx.x * 256 + tid;  // 0..1023
    const int b = blockIdx.y;
    const int i = pos >> 5, j = pos & 31;
    const int pr1 = (2 * i + 1 == 63) ? 0 : 2 * i + 1; // wrapped conv row
    const int pc1 = (2 * j + 1 == 63) ? 0 : 2 * j + 1;
    int R[4]  = {2 * i, 2 * i + 1, pr1, pr1 + 1};
    int Cc[4] = {2 * j, 2 * j + 1, pc1, pc1 + 1};

    const float* xb = x + (size_t)b * 4096;
    float rp[16], rn[16];
#pragma unroll
    for (int a = 0; a < 4; a++)
#pragma unroll
        for (int c = 0; c < 4; c++) {
            float v = xb[R[a] * 64 + Cc[c]];
            rp[a * 4 + c] = fmaxf(v, 0.f);
            rn[a * 4 + c] = fmaxf(-v, 0.f);
        }

    float* ob = out + (size_t)b * 64 * 1024 + i * 32 + j;
#pragma unroll 8
    for (int oc = 0; oc < 64; oc++) {
        const float* w = &ws[oc * 8];
        const float bias = bs[oc];
        float acc = 0.f;
#pragma unroll
        for (int P = 0; P < 2; P++)
#pragma unroll
            for (int Q = 0; Q < 2; Q++) {
                float s = bias;
#pragma unroll
                for (int kh = 0; kh < 2; kh++)
#pragma unroll
                    for (int kw = 0; kw < 2; kw++) {
                        int idx = (2 * P + kh) * 4 + (2 * Q + kw);
                        s = fmaf(rp[idx], w[kh * 2 + kw], s);
                        s = fmaf(rn[idx], w[4 + kh * 2 + kw], s);
                    }
                acc += fmaxf(s, 0.f);
            }
        ob[oc * 1024] = 0.25f * acc;
    }
}

// ---------------------------------------------------------------------------
// Recursion level: in [B][Nin=G*G][16][S][S] -> grouped conv2x2 (16 -> 4*16)
// + bias, block shuffle, relu, wrap-pad, avgpool2 ->
// out [B][4*Nin][16][S/2][S/2]
// CTA = (group n, batch chunk of BB). Thread unit = 16 out channels of one
// child block at one pooled output (4 conv taps), using packed f32x2 FMA.
// ---------------------------------------------------------------------------
template <int S, int BB, int G>
__global__ __launch_bounds__(256)
void k_layer(const float* __restrict__ in, const float* __restrict__ W,
             const float* __restrict__ bias, float* __restrict__ out)
{
    constexpr int s = S - 1;          // conv output extent
    constexpr int H = S / 2;          // pooled extent
    constexpr int Nin = G * G;
    constexpr int Nout = 4 * Nin;
    constexpr int RS = S + 1;         // padded smem row stride
    constexpr int CHB = 16 * S * RS + 4; // per-batch-slot input stride
    constexpr int WCS = 1028;         // per-child weight stride (bank-skewed)
    constexpr int perB = 16 * S * S;

    extern __shared__ float sm[];
    float* ws  = sm;                  // 4 * WCS : ws[child][tap(ci*4+kh*2+kw)][c]
    float* bs  = sm + 4 * WCS;        // 64
    float* ins = bs + 64;             // BB * CHB

    const int tid = threadIdx.x;
    const int n = blockIdx.x;
    const int b0 = blockIdx.y * BB;

    // Weights: rows n*64 .. n*64+63, 64 elems each (coalesced read, reordered)
    const float* Wg = W + (size_t)n * 64 * 64;
    for (int t = tid; t < 4096; t += 256) {
        int ol = t >> 6;   // out-channel within group
        int tap = t & 63;  // ci*4 + kh*2 + kw
        int child = ol >> 4, c = ol & 15;
        ws[child * WCS + tap * 16 + c] = Wg[t];
    }
    if (tid < 64) bs[tid] = bias[n * 64 + tid];

    // Inputs (coalesced)
    for (int t = tid; t < BB * perB; t += 256) {
        int bl = t / perB, rem = t - bl * perB;
        int ci = rem / (S * S);
        int sp = rem - ci * S * S;
        int r = sp / S, q = sp - r * S;
        ins[bl * CHB + ci * (S * RS) + r * RS + q] =
            in[((size_t)(b0 + bl) * Nin + n) * perB + rem];
    }
    __syncthreads();

    const int Ay = n / G, Ax = n % G;

    constexpr int UNITS = BB * 4 * H * H; // multiple of 256 for all configs
    for (int u = tid; u < UNITS; u += 256) {
        const int j = u % H;
        const int i = (u / H) % H;
        const int child = (u / (H * H)) & 3;
        const int bl = u / (4 * H * H);

        const int pr0 = 2 * i, pc0 = 2 * j;
        const int pr1 = (2 * i + 1 == s) ? 0 : 2 * i + 1;
        const int pc1 = (2 * j + 1 == s) ? 0 : 2 * j + 1;

        const float* wc = ws + child * WCS;
        const float* ib = ins + bl * CHB;

        f2_t acc[8][4];
#pragma unroll
        for (int k = 0; k < 8; k++) {
            f2_t bv = pk2(bs[child * 16 + 2 * k], bs[child * 16 + 2 * k + 1]);
            acc[k][0] = bv; acc[k][1] = bv; acc[k][2] = bv; acc[k][3] = bv;
        }

#pragma unroll 4
        for (int ci = 0; ci < 16; ci++) {
            const float* ic = ib + ci * (S * RS);
#pragma unroll
            for (int kh = 0; kh < 2; kh++) {
                const int ra = (pr0 + kh) * RS;
                const int rb = (pr1 + kh) * RS;
#pragma unroll
                for (int kw = 0; kw < 2; kw++) {
                    const float* wt = wc + (ci * 4 + kh * 2 + kw) * 16;
                    float v0 = ic[ra + pc0 + kw];
                    float v1 = ic[ra + pc1 + kw];
                    float v2 = ic[rb + pc0 + kw];
                    float v3 = ic[rb + pc1 + kw];
                    f2_t vs0 = pk2(v0, v0), vs1 = pk2(v1, v1);
                    f2_t vs2 = pk2(v2, v2), vs3 = pk2(v3, v3);
#pragma unroll
                    for (int k = 0; k < 8; k++) {
                        f2_t w2 = *(const f2_t*)(wt + 2 * k);
                        acc[k][0] = fma2(w2, vs0, acc[k][0]);
                        acc[k][1] = fma2(w2, vs1, acc[k][1]);
                        acc[k][2] = fma2(w2, vs2, acc[k][2]);
                        acc[k][3] = fma2(w2, vs3, acc[k][3]);
                    }
                }
            }
        }

        // Epilogue: relu each tap, average, write to shuffled child block.
        const int yl = child >> 1, xl = child & 1;
        const int nprime = (2 * Ay + yl) * (2 * G) + (2 * Ax + xl);
        float* ob = out + ((size_t)(b0 + bl) * Nout + nprime) * 16 * (H * H)
                        + i * H + j;
#pragma unroll
        for (int k = 0; k < 8; k++) {
            float a0, c0, a1, c1, a2, c2, a3, c3;
            upk2(acc[k][0], a0, c0);
            upk2(acc[k][1], a1, c1);
            upk2(acc[k][2], a2, c2);
            upk2(acc[k][3], a3, c3);
            float e = fmaxf(a0, 0.f) + fmaxf(a1, 0.f) + fmaxf(a2, 0.f) + fmaxf(a3, 0.f);
            float o = fmaxf(c0, 0.f) + fmaxf(c1, 0.f) + fmaxf(c2, 0.f) + fmaxf(c3, 0.f);
            ob[(2 * k) * (H * H)]     = 0.25f * e;
            ob[(2 * k + 1) * (H * H)] = 0.25f * o;
        }
    }
}

// ---------------------------------------------------------------------------
// FT layer: v[B,4096,16] x Wft[4096,4,16] + bft -> (real,imag) [B,2,64,64]
// ---------------------------------------------------------------------------
__global__ __launch_bounds__(256)
void k_ft(const float* __restrict__ v, const float* __restrict__ Wft,
          const float* __restrict__ bft, float* __restrict__ out)
{
    const int n = blockIdx.x * 256 + threadIdx.x; // 0..4095
    const int b = blockIdx.y;
    const float* vp = v + ((size_t)b * 4096 + n) * 16;
    float vv[16];
#pragma unroll
    for (int c = 0; c < 16; c += 4) {
        float4 t = *(const float4*)(vp + c);
        vv[c] = t.x; vv[c + 1] = t.y; vv[c + 2] = t.z; vv[c + 3] = t.w;
    }
    const float* wp = Wft + (size_t)n * 64;
    float f[4];
#pragma unroll
    for (int o = 0; o < 4; o++) {
        float acc = bft[n * 4 + o];
#pragma unroll
        for (int c = 0; c < 16; c++) acc = fmaf(vv[c], wp[o * 16 + c], acc);
        f[o] = acc;
    }
    out[(size_t)b * 8192 + n]        = f[0] - f[1];
    out[(size_t)b * 8192 + 4096 + n] = f[2] - f[3];
}

// ---------------------------------------------------------------------------

static inline int smem_bytes(int S, int BB) {
    return (4 * 1028 + 64 + BB * (16 * S * (S + 1) + 4)) * 4;
}

extern "C" void kernel_launch(void* const* d_in, const int* in_sizes, int n_in,
                              void* d_out, int out_size)
{
    (void)n_in; (void)out_size;
    const float* x  = (const float*)d_in[0];
    const float* W0 = (const float*)d_in[1];
    const float* b0 = (const float*)d_in[2];
    const float *W1, *b1, *W2, *b2, *W3, *b3, *W4, *b4, *W5, *b5, *Wft, *bft;
    if (in_sizes[3] == 262144) {
        // setup_inputs dict order: x,W0,b0,Wft,bft,W1,b1,...,W5,b5
        Wft = (const float*)d_in[3];  bft = (const float*)d_in[4];
        W1 = (const float*)d_in[5];   b1 = (const float*)d_in[6];
        W2 = (const float*)d_in[7];   b2 = (const float*)d_in[8];
        W3 = (const float*)d_in[9];   b3 = (const float*)d_in[10];
        W4 = (const float*)d_in[11];  b4 = (const float*)d_in[12];
        W5 = (const float*)d_in[13];  b5 = (const float*)d_in[14];
    } else {
        // reference signature order: x,W0,b0,W1,b1,...,W5,b5,Wft,bft
        W1 = (const float*)d_in[3];   b1 = (const float*)d_in[4];
        W2 = (const float*)d_in[5];   b2 = (const float*)d_in[6];
        W3 = (const float*)d_in[7];   b3 = (const float*)d_in[8];
        W4 = (const float*)d_in[9];   b4 = (const float*)d_in[10];
        W5 = (const float*)d_in[11];  b5 = (const float*)d_in[12];
        Wft = (const float*)d_in[13]; bft = (const float*)d_in[14];
    }
    float* out = (float*)d_out;

    float *bufA, *bufB;
    cudaGetSymbolAddress((void**)&bufA, g_bufA);
    cudaGetSymbolAddress((void**)&bufB, g_bufB);

    const int s1 = smem_bytes(32, 1);
    const int s2 = smem_bytes(16, 2);
    const int s3 = smem_bytes(8, 8);
    const int s4 = smem_bytes(4, 32);
    const int s5 = smem_bytes(2, 128);
    cudaFuncSetAttribute(k_layer<32, 1, 2>,   cudaFuncAttributeMaxDynamicSharedMemorySize, s1);
    cudaFuncSetAttribute(k_layer<16, 2, 4>,   cudaFuncAttributeMaxDynamicSharedMemorySize, s2);
    cudaFuncSetAttribute(k_layer<8, 8, 8>,    cudaFuncAttributeMaxDynamicSharedMemorySize, s3);
    cudaFuncSetAttribute(k_layer<4, 32, 16>,  cudaFuncAttributeMaxDynamicSharedMemorySize, s4);
    cudaFuncSetAttribute(k_layer<2, 128, 32>, cudaFuncAttributeMaxDynamicSharedMemorySize, s5);

    k_layer0<<<dim3(4, BATCH), 256>>>(x, W0, b0, bufA);
    k_layer<32, 1, 2><<<dim3(4, 256), 256, s1>>>(bufA, W1, b1, bufB);
    k_layer<16, 2, 4><<<dim3(16, 128), 256, s2>>>(bufB, W2, b2, bufA);
    k_layer<8, 8, 8><<<dim3(64, 32), 256, s3>>>(bufA, W3, b3, bufB);
    k_layer<4, 32, 16><<<dim3(256, 8), 256, s4>>>(bufB, W4, b4, bufA);
    k_layer<2, 128, 32><<<dim3(1024, 2), 256, s5>>>(bufA, W5, b5, bufB);
    k_ft<<<dim3(16, BATCH), 256>>>(bufB, Wft, bft, out);
}

// round 2
// speedup vs baseline: 1.6913x; 1.6913x over previous
#include <cuda_runtime.h>
#include <cstdint>

// ---------------------------------------------------------------------------
// ButterFlyNet2D forward, fully fused per level.
// Activations: [B][Nblocks][C=16][S][S] (level 1 == NCHW [B][64][32][32]).
// ---------------------------------------------------------------------------

#define BATCH 256

__device__ float g_bufA[BATCH * 64 * 32 * 32]; // 64 MB
__device__ float g_bufB[BATCH * 64 * 32 * 32];

// ---- packed f32x2 helpers (Blackwell FFMA2 path) --------------------------
typedef unsigned long long f2_t;

__device__ __forceinline__ f2_t pk2(float a, float b) {
    f2_t r;
    asm("mov.b64 %0, {%1, %2};" : "=l"(r)
        : "r"(__float_as_uint(a)), "r"(__float_as_uint(b)));
    return r;
}
__device__ __forceinline__ void upk2(f2_t v, float& a, float& b) {
    unsigned lo, hi;
    asm("mov.b64 {%0, %1}, %2;" : "=r"(lo), "=r"(hi) : "l"(v));
    a = __uint_as_float(lo);
    b = __uint_as_float(hi);
}
__device__ __forceinline__ f2_t fma2(f2_t a, f2_t b, f2_t c) {
    f2_t d;
    asm("fma.rn.f32x2 %0, %1, %2, %3;" : "=l"(d) : "l"(a), "l"(b), "l"(c));
    return d;
}

// ---------------------------------------------------------------------------
// Layer 0: x[B,1,64,64] -> split(relu(x),relu(-x),0,0) -> conv2x2(4->64)
//          -> +b0 -> relu -> wrap-pad -> avgpool2   => out[B,64,32,32]
// ---------------------------------------------------------------------------
__global__ __launch_bounds__(256)
void k_layer0(const float* __restrict__ x, const float* __restrict__ W0,
              const float* __restrict__ b0, float* __restrict__ out)
{
    __shared__ float ws[512]; // [oc][ic(0..1)][kh][kw]
    __shared__ float bs[64];
    const int tid = threadIdx.x;
    for (int t = tid; t < 512; t += 256) {
        int oc = t >> 3, r = t & 7;
        ws[t] = W0[oc * 16 + r];
    }
    if (tid < 64) bs[tid] = b0[tid];
    __syncthreads();

    const int pos = blockIdx.x * 256 + tid;  // 0..1023
    const int b = blockIdx.y;
    const int i = pos >> 5, j = pos & 31;
    const int pr1 = (2 * i + 1 == 63) ? 0 : 2 * i + 1;
    const int pc1 = (2 * j + 1 == 63) ? 0 : 2 * j + 1;
    int R[4]  = {2 * i, 2 * i + 1, pr1, pr1 + 1};
    int Cc[4] = {2 * j, 2 * j + 1, pc1, pc1 + 1};

    const float* xb = x + (size_t)b * 4096;
    float rp[16], rn[16];
#pragma unroll
    for (int a = 0; a < 4; a++)
#pragma unroll
        for (int c = 0; c < 4; c++) {
            float v = xb[R[a] * 64 + Cc[c]];
            rp[a * 4 + c] = fmaxf(v, 0.f);
            rn[a * 4 + c] = fmaxf(-v, 0.f);
        }

    float* ob = out + (size_t)b * 64 * 1024 + i * 32 + j;
#pragma unroll 8
    for (int oc = 0; oc < 64; oc++) {
        const float* w = &ws[oc * 8];
        const float bias = bs[oc];
        float acc = 0.f;
#pragma unroll
        for (int P = 0; P < 2; P++)
#pragma unroll
            for (int Q = 0; Q < 2; Q++) {
                float s = bias;
#pragma unroll
                for (int kh = 0; kh < 2; kh++)
#pragma unroll
                    for (int kw = 0; kw < 2; kw++) {
                        int idx = (2 * P + kh) * 4 + (2 * Q + kw);
                        s = fmaf(rp[idx], w[kh * 2 + kw], s);
                        s = fmaf(rn[idx], w[4 + kh * 2 + kw], s);
                    }
                acc += fmaxf(s, 0.f);
            }
        ob[oc * 1024] = 0.25f * acc;
    }
}

// ---------------------------------------------------------------------------
// Recursion level: grouped conv2x2 (16 -> 64) + bias, block shuffle, relu,
// wrap-pad, avgpool2. CTA = (group n, batch chunk BB).
// Thread unit = 16 out channels of one child at one pooled output (4 taps),
// packed f32x2 FMA. 2 CTAs/SM enforced (<=128 regs).
// ---------------------------------------------------------------------------
template <int S, int BB, int G>
__global__ __launch_bounds__(256, 2)
void k_layer(const float* __restrict__ in, const float* __restrict__ W,
             const float* __restrict__ bias, float* __restrict__ out)
{
    constexpr int s = S - 1;
    constexpr int H = S / 2;
    constexpr int Nin = G * G;
    constexpr int Nout = 4 * Nin;
    constexpr int RS = S + 1;
    constexpr int CHB = 16 * S * RS + 4;
    constexpr int WCS = 1028;            // per-child weight stride (floats)
    constexpr int perB = 16 * S * S;

    extern __shared__ float sm[];
    float* ws  = sm;                  // 4*WCS : ws[child][tap(ci*4+kh*2+kw)][c]
    float* bs  = sm + 4 * WCS;        // 64
    float* ins = bs + 64;             // BB * CHB

    const int tid = threadIdx.x;
    const int n = blockIdx.x;
    const int b0 = blockIdx.y * BB;

    const float* Wg = W + (size_t)n * 64 * 64;
    for (int t = tid; t < 4096; t += 256) {
        int ol = t >> 6;
        int tap = t & 63;
        int child = ol >> 4, c = ol & 15;
        ws[child * WCS + tap * 16 + c] = Wg[t];
    }
    if (tid < 64) bs[tid] = bias[n * 64 + tid];

    for (int t = tid; t < BB * perB; t += 256) {
        int bl = t / perB, rem = t - bl * perB;
        int ci = rem / (S * S);
        int sp = rem - ci * S * S;
        int r = sp / S, q = sp - r * S;
        ins[bl * CHB + ci * (S * RS) + r * RS + q] =
            in[((size_t)(b0 + bl) * Nin + n) * perB + rem];
    }
    __syncthreads();

    const int Ay = n / G, Ax = n % G;

    constexpr int UNITS = BB * 4 * H * H;
    for (int u = tid; u < UNITS; u += 256) {
        const int j = u % H;
        const int i = (u / H) % H;
        const int child = (u / (H * H)) & 3;
        const int bl = u / (4 * H * H);

        const int pr0 = 2 * i, pc0 = 2 * j;
        const int pr1 = (2 * i + 1 == s) ? 0 : 2 * i + 1;
        const int pc1 = (2 * j + 1 == s) ? 0 : 2 * j + 1;

        const float* wc = ws + child * WCS;
        const float* ib = ins + bl * CHB;

        f2_t acc[8][4];
#pragma unroll
        for (int k = 0; k < 8; k++) {
            f2_t bv = pk2(bs[child * 16 + 2 * k], bs[child * 16 + 2 * k + 1]);
            acc[k][0] = bv; acc[k][1] = bv; acc[k][2] = bv; acc[k][3] = bv;
        }

#pragma unroll 4
        for (int ci = 0; ci < 16; ci++) {
            const float* ic = ib + ci * (S * RS);
#pragma unroll
            for (int kh = 0; kh < 2; kh++) {
                const int ra = (pr0 + kh) * RS;
                const int rb = (pr1 + kh) * RS;
#pragma unroll
                for (int kw = 0; kw < 2; kw++) {
                    // weights for this tap: 16 floats, 16B-aligned -> 4x LDS.128
                    const ulonglong2* wt2 =
                        (const ulonglong2*)(wc + (ci * 4 + kh * 2 + kw) * 16);
                    float v0 = ic[ra + pc0 + kw];
                    float v1 = ic[ra + pc1 + kw];
                    float v2 = ic[rb + pc0 + kw];
                    float v3 = ic[rb + pc1 + kw];
                    f2_t vs0 = pk2(v0, v0), vs1 = pk2(v1, v1);
                    f2_t vs2 = pk2(v2, v2), vs3 = pk2(v3, v3);
#pragma unroll
                    for (int m = 0; m < 4; m++) {
                        ulonglong2 ww = wt2[m];
                        acc[2 * m][0]     = fma2(ww.x, vs0, acc[2 * m][0]);
                        acc[2 * m][1]     = fma2(ww.x, vs1, acc[2 * m][1]);
                        acc[2 * m][2]     = fma2(ww.x, vs2, acc[2 * m][2]);
                        acc[2 * m][3]     = fma2(ww.x, vs3, acc[2 * m][3]);
                        acc[2 * m + 1][0] = fma2(ww.y, vs0, acc[2 * m + 1][0]);
                        acc[2 * m + 1][1] = fma2(ww.y, vs1, acc[2 * m + 1][1]);
                        acc[2 * m + 1][2] = fma2(ww.y, vs2, acc[2 * m + 1][2]);
                        acc[2 * m + 1][3] = fma2(ww.y, vs3, acc[2 * m + 1][3]);
                    }
                }
            }
        }

        const int yl = child >> 1, xl = child & 1;
        const int nprime = (2 * Ay + yl) * (2 * G) + (2 * Ax + xl);
        float* ob = out + ((size_t)(b0 + bl) * Nout + nprime) * 16 * (H * H)
                        + i * H + j;
#pragma unroll
        for (int k = 0; k < 8; k++) {
            float a0, c0, a1, c1, a2, c2, a3, c3;
            upk2(acc[k][0], a0, c0);
            upk2(acc[k][1], a1, c1);
            upk2(acc[k][2], a2, c2);
            upk2(acc[k][3], a3, c3);
            float e = fmaxf(a0, 0.f) + fmaxf(a1, 0.f) + fmaxf(a2, 0.f) + fmaxf(a3, 0.f);
            float o = fmaxf(c0, 0.f) + fmaxf(c1, 0.f) + fmaxf(c2, 0.f) + fmaxf(c3, 0.f);
            ob[(2 * k) * (H * H)]     = 0.25f * e;
            ob[(2 * k + 1) * (H * H)] = 0.25f * o;
        }
    }
}

// ---------------------------------------------------------------------------
// FT layer: v[B,4096,16] x Wft[4096,4,16] + bft -> (real,imag) [B,2,64,64]
// ---------------------------------------------------------------------------
__global__ __launch_bounds__(256)
void k_ft(const float* __restrict__ v, const float* __restrict__ Wft,
          const float* __restrict__ bft, float* __restrict__ out)
{
    const int n = blockIdx.x * 256 + threadIdx.x;
    const int b = blockIdx.y;
    const float* vp = v + ((size_t)b * 4096 + n) * 16;
    float vv[16];
#pragma unroll
    for (int c = 0; c < 16; c += 4) {
        float4 t = *(const float4*)(vp + c);
        vv[c] = t.x; vv[c + 1] = t.y; vv[c + 2] = t.z; vv[c + 3] = t.w;
    }
    const float* wp = Wft + (size_t)n * 64;
    float f[4];
#pragma unroll
    for (int o = 0; o < 4; o++) {
        float acc = bft[n * 4 + o];
#pragma unroll
        for (int c = 0; c < 16; c++) acc = fmaf(vv[c], wp[o * 16 + c], acc);
        f[o] = acc;
    }
    out[(size_t)b * 8192 + n]        = f[0] - f[1];
    out[(size_t)b * 8192 + 4096 + n] = f[2] - f[3];
}

// ---------------------------------------------------------------------------

static inline int smem_bytes(int S, int BB) {
    return (4 * 1028 + 64 + BB * (16 * S * (S + 1) + 4)) * 4;
}

extern "C" void kernel_launch(void* const* d_in, const int* in_sizes, int n_in,
                              void* d_out, int out_size)
{
    (void)n_in; (void)out_size;
    const float* x  = (const float*)d_in[0];
    const float* W0 = (const float*)d_in[1];
    const float* b0 = (const float*)d_in[2];
    const float *W1, *b1, *W2, *b2, *W3, *b3, *W4, *b4, *W5, *b5, *Wft, *bft;
    if (in_sizes[3] == 262144) {
        Wft = (const float*)d_in[3];  bft = (const float*)d_in[4];
        W1 = (const float*)d_in[5];   b1 = (const float*)d_in[6];
        W2 = (const float*)d_in[7];   b2 = (const float*)d_in[8];
        W3 = (const float*)d_in[9];   b3 = (const float*)d_in[10];
        W4 = (const float*)d_in[11];  b4 = (const float*)d_in[12];
        W5 = (const float*)d_in[13];  b5 = (const float*)d_in[14];
    } else {
        W1 = (const float*)d_in[3];   b1 = (const float*)d_in[4];
        W2 = (const float*)d_in[5];   b2 = (const float*)d_in[6];
        W3 = (const float*)d_in[7];   b3 = (const float*)d_in[8];
        W4 = (const float*)d_in[9];   b4 = (const float*)d_in[10];
        W5 = (const float*)d_in[11];  b5 = (const float*)d_in[12];
        Wft = (const float*)d_in[13]; bft = (const float*)d_in[14];
    }
    float* out = (float*)d_out;

    float *bufA, *bufB;
    cudaGetSymbolAddress((void**)&bufA, g_bufA);
    cudaGetSymbolAddress((void**)&bufB, g_bufB);

    const int s1 = smem_bytes(32, 1);
    const int s2 = smem_bytes(16, 2);
    const int s3 = smem_bytes(8, 8);
    const int s4 = smem_bytes(4, 32);
    const int s5 = smem_bytes(2, 128);
    cudaFuncSetAttribute(k_layer<32, 1, 2>,   cudaFuncAttributeMaxDynamicSharedMemorySize, s1);
    cudaFuncSetAttribute(k_layer<16, 2, 4>,   cudaFuncAttributeMaxDynamicSharedMemorySize, s2);
    cudaFuncSetAttribute(k_layer<8, 8, 8>,    cudaFuncAttributeMaxDynamicSharedMemorySize, s3);
    cudaFuncSetAttribute(k_layer<4, 32, 16>,  cudaFuncAttributeMaxDynamicSharedMemorySize, s4);
    cudaFuncSetAttribute(k_layer<2, 128, 32>, cudaFuncAttributeMaxDynamicSharedMemorySize, s5);

    k_layer0<<<dim3(4, BATCH), 256>>>(x, W0, b0, bufA);
    k_layer<32, 1, 2><<<dim3(4, 256), 256, s1>>>(bufA, W1, b1, bufB);
    k_layer<16, 2, 4><<<dim3(16, 128), 256, s2>>>(bufB, W2, b2, bufA);
    k_layer<8, 8, 8><<<dim3(64, 32), 256, s3>>>(bufA, W3, b3, bufB);
    k_layer<4, 32, 16><<<dim3(256, 8), 256, s4>>>(bufB, W4, b4, bufA);
    k_layer<2, 128, 32><<<dim3(1024, 2), 256, s5>>>(bufA, W5, b5, bufB);
    k_ft<<<dim3(16, BATCH), 256>>>(bufB, Wft, bft, out);
}

// round 3
// speedup vs baseline: 1.7677x; 1.0452x over previous
#include <cuda_runtime.h>
#include <cstdint>

// ---------------------------------------------------------------------------
// ButterFlyNet2D forward, fully fused per level.
// Activations: [B][Nblocks][C=16][S][S] (level 1 == NCHW [B][64][32][32]).
// ---------------------------------------------------------------------------

#define BATCH 256

__device__ float g_bufA[BATCH * 64 * 32 * 32]; // 64 MB
__device__ float g_bufB[BATCH * 64 * 32 * 32];

// ---- packed f32x2 helpers (Blackwell FFMA2 path) --------------------------
typedef unsigned long long f2_t;

__device__ __forceinline__ f2_t pk2(float a, float b) {
    f2_t r;
    asm("mov.b64 %0, {%1, %2};" : "=l"(r)
        : "r"(__float_as_uint(a)), "r"(__float_as_uint(b)));
    return r;
}
__device__ __forceinline__ void upk2(f2_t v, float& a, float& b) {
    unsigned lo, hi;
    asm("mov.b64 {%0, %1}, %2;" : "=r"(lo), "=r"(hi) : "l"(v));
    a = __uint_as_float(lo);
    b = __uint_as_float(hi);
}
__device__ __forceinline__ f2_t fma2(f2_t a, f2_t b, f2_t c) {
    f2_t d;
    asm("fma.rn.f32x2 %0, %1, %2, %3;" : "=l"(d) : "l"(a), "l"(b), "l"(c));
    return d;
}

// ---------------------------------------------------------------------------
// Layer 0: x[B,1,64,64] -> split(relu(x),relu(-x),0,0) -> conv2x2(4->64)
//          -> +b0 -> relu -> wrap-pad -> avgpool2   => out[B,64,32,32]
// ---------------------------------------------------------------------------
__global__ __launch_bounds__(256)
void k_layer0(const float* __restrict__ x, const float* __restrict__ W0,
              const float* __restrict__ b0, float* __restrict__ out)
{
    __shared__ float ws[512]; // [oc][ic(0..1)][kh][kw]
    __shared__ float bs[64];
    const int tid = threadIdx.x;
    for (int t = tid; t < 512; t += 256) {
        int oc = t >> 3, r = t & 7;
        ws[t] = W0[oc * 16 + r];
    }
    if (tid < 64) bs[tid] = b0[tid];
    __syncthreads();

    const int pos = blockIdx.x * 256 + tid;  // 0..1023
    const int b = blockIdx.y;
    const int i = pos >> 5, j = pos & 31;
    const int pr1 = (2 * i + 1 == 63) ? 0 : 2 * i + 1;
    const int pc1 = (2 * j + 1 == 63) ? 0 : 2 * j + 1;
    int R[4]  = {2 * i, 2 * i + 1, pr1, pr1 + 1};
    int Cc[4] = {2 * j, 2 * j + 1, pc1, pc1 + 1};

    const float* xb = x + (size_t)b * 4096;
    float rp[16], rn[16];
#pragma unroll
    for (int a = 0; a < 4; a++)
#pragma unroll
        for (int c = 0; c < 4; c++) {
            float v = xb[R[a] * 64 + Cc[c]];
            rp[a * 4 + c] = fmaxf(v, 0.f);
            rn[a * 4 + c] = fmaxf(-v, 0.f);
        }

    float* ob = out + (size_t)b * 64 * 1024 + i * 32 + j;
#pragma unroll 8
    for (int oc = 0; oc < 64; oc++) {
        const float* w = &ws[oc * 8];
        const float bias = bs[oc];
        float acc = 0.f;
#pragma unroll
        for (int P = 0; P < 2; P++)
#pragma unroll
            for (int Q = 0; Q < 2; Q++) {
                float s = bias;
#pragma unroll
                for (int kh = 0; kh < 2; kh++)
#pragma unroll
                    for (int kw = 0; kw < 2; kw++) {
                        int idx = (2 * P + kh) * 4 + (2 * Q + kw);
                        s = fmaf(rp[idx], w[kh * 2 + kw], s);
                        s = fmaf(rn[idx], w[4 + kh * 2 + kw], s);
                    }
                acc += fmaxf(s, 0.f);
            }
        ob[oc * 1024] = 0.25f * acc;
    }
}

// ---------------------------------------------------------------------------
// Recursion level: grouped conv2x2 (16 -> 64) + bias, block shuffle, relu,
// wrap-pad, avgpool2. CTA = (group n, batch chunk BB).
// Inputs stored in smem as parity planes: cell (r,c) -> [r&1][c&1][r>>1][c>>1]
// => every inner-loop LDS is warp-contiguous (conflict-free); warps are
// child-uniform so weight LDS.128 is a pure broadcast.
// ---------------------------------------------------------------------------
template <int S, int BB, int G>
__global__ __launch_bounds__(256, 2)
void k_layer(const float* __restrict__ in, const float* __restrict__ W,
             const float* __restrict__ bias, float* __restrict__ out)
{
    constexpr int H = S / 2;
    constexpr int HH = H * H;
    constexpr int Nin = G * G;
    constexpr int Nout = 4 * Nin;
    constexpr int CB = S * S;                    // per-ci plane block (floats)
    constexpr int PAD = (HH < 32) ? HH : 0;      // bl-stride bank offset
    constexpr int CHB = 16 * CB + PAD;
    constexpr int WCS = 1024;
    constexpr int perB = 16 * S * S;
    constexpr int ITERS = (BB * HH) / 64;        // units per child / 64 workers

    extern __shared__ float sm[];
    float* ws  = sm;              // 4*WCS : ws[child][tap(ci*4+kh*2+kw)][c]
    float* bs  = sm + 4 * WCS;    // 64
    float* ins = bs + 64;         // BB * CHB

    const int tid = threadIdx.x;
    const int n = blockIdx.x;
    const int b0 = blockIdx.y * BB;

    const float* Wg = W + (size_t)n * 4096;
    for (int t = tid; t < 4096; t += 256) {
        int ol = t >> 6, tap = t & 63;
        ws[(ol >> 4) * WCS + tap * 16 + (ol & 15)] = Wg[t];
    }
    if (tid < 64) bs[tid] = bias[n * 64 + tid];

    for (int t = tid; t < BB * perB; t += 256) {
        int bl = t / perB, rem = t - bl * perB;
        int ci = rem / CB, sp = rem - ci * CB;
        int r = sp / S, c = sp - r * S;
        ins[bl * CHB + ci * CB + ((r & 1) * 2 + (c & 1)) * HH
            + (r >> 1) * H + (c >> 1)]
            = in[((size_t)(b0 + bl) * Nin + n) * perB + rem];
    }
    __syncthreads();

    const int Ay = n / G, Ax = n % G;
    const int lane = tid & 31, warp = tid >> 5;
    const int child = warp & 3;
    const int wk0 = lane + ((warp >> 2) << 5);   // 0..63 worker within child

    const float* wc = ws + child * WCS;
    const int yl = child >> 1, xl = child & 1;

#pragma unroll
    for (int it = 0; it < ITERS; it++) {
        const int v = wk0 + (it << 6);
        const int j = v % H;
        const int i = (v / H) % H;
        const int bl = v / HH;

        const bool wi = (i == H - 1);
        const bool wj = (j == H - 1);
        // row terms: parity*2HH + idx*H ; a = P*2+kh
        const int rt0 = i * H;
        const int rt1 = 2 * HH + i * H;
        const int rt2 = wi ? 0 : rt1;                 // row pr1
        const int rt3 = wi ? 2 * HH : (i + 1) * H;    // row pr1+1
        // col terms: parity*HH + idx ; b = Q*2+kw
        const int ct0 = j;
        const int ct1 = HH + j;
        const int ct2 = wj ? 0 : ct1;                 // col pc1
        const int ct3 = wj ? HH : (j + 1);            // col pc1+1
        const int rt[4] = {rt0, rt1, rt2, rt3};
        const int ct[4] = {ct0, ct1, ct2, ct3};

        const float* ib = ins + bl * CHB;

        f2_t acc[8][4];
#pragma unroll
        for (int k = 0; k < 8; k++) {
            f2_t bv = pk2(bs[child * 16 + 2 * k], bs[child * 16 + 2 * k + 1]);
            acc[k][0] = bv; acc[k][1] = bv; acc[k][2] = bv; acc[k][3] = bv;
        }

#pragma unroll 4
        for (int ci = 0; ci < 16; ci++) {
            const float* cb = ib + ci * CB;
            float xv[4][4];
#pragma unroll
            for (int a = 0; a < 4; a++)
#pragma unroll
                for (int b = 0; b < 4; b++)
                    xv[a][b] = cb[rt[a] + ct[b]];

#pragma unroll
            for (int kh = 0; kh < 2; kh++)
#pragma unroll
                for (int kw = 0; kw < 2; kw++) {
                    const ulonglong2* wt2 =
                        (const ulonglong2*)(wc + (ci * 4 + kh * 2 + kw) * 16);
                    // splat per pooled tap (P,Q): value x[2P+kh][2Q+kw]
                    f2_t vs0 = pk2(xv[kh][kw],         xv[kh][kw]);
                    f2_t vs1 = pk2(xv[kh][2 + kw],     xv[kh][2 + kw]);
                    f2_t vs2 = pk2(xv[2 + kh][kw],     xv[2 + kh][kw]);
                    f2_t vs3 = pk2(xv[2 + kh][2 + kw], xv[2 + kh][2 + kw]);
#pragma unroll
                    for (int m = 0; m < 4; m++) {
                        ulonglong2 ww = wt2[m];
                        acc[2 * m][0]     = fma2(ww.x, vs0, acc[2 * m][0]);
                        acc[2 * m][1]     = fma2(ww.x, vs1, acc[2 * m][1]);
                        acc[2 * m][2]     = fma2(ww.x, vs2, acc[2 * m][2]);
                        acc[2 * m][3]     = fma2(ww.x, vs3, acc[2 * m][3]);
                        acc[2 * m + 1][0] = fma2(ww.y, vs0, acc[2 * m + 1][0]);
                        acc[2 * m + 1][1] = fma2(ww.y, vs1, acc[2 * m + 1][1]);
                        acc[2 * m + 1][2] = fma2(ww.y, vs2, acc[2 * m + 1][2]);
                        acc[2 * m + 1][3] = fma2(ww.y, vs3, acc[2 * m + 1][3]);
                    }
                }
        }

        const int nprime = (2 * Ay + yl) * (2 * G) + (2 * Ax + xl);
        float* ob = out + ((size_t)(b0 + bl) * Nout + nprime) * 16 * HH
                        + i * H + j;
#pragma unroll
        for (int k = 0; k < 8; k++) {
            float a0, c0, a1, c1, a2, c2, a3, c3;
            upk2(acc[k][0], a0, c0);
            upk2(acc[k][1], a1, c1);
            upk2(acc[k][2], a2, c2);
            upk2(acc[k][3], a3, c3);
            float e = fmaxf(a0, 0.f) + fmaxf(a1, 0.f) + fmaxf(a2, 0.f) + fmaxf(a3, 0.f);
            float o = fmaxf(c0, 0.f) + fmaxf(c1, 0.f) + fmaxf(c2, 0.f) + fmaxf(c3, 0.f);
            ob[(2 * k) * HH]     = 0.25f * e;
            ob[(2 * k + 1) * HH] = 0.25f * o;
        }
    }
}

// ---------------------------------------------------------------------------
// FT layer: v[B,4096,16] x Wft[4096,4,16] + bft -> (real,imag) [B,2,64,64]
// ---------------------------------------------------------------------------
__global__ __launch_bounds__(256)
void k_ft(const float* __restrict__ v, const float* __restrict__ Wft,
          const float* __restrict__ bft, float* __restrict__ out)
{
    const int n = blockIdx.x * 256 + threadIdx.x;
    const int b = blockIdx.y;
    const float* vp = v + ((size_t)b * 4096 + n) * 16;
    float vv[16];
#pragma unroll
    for (int c = 0; c < 16; c += 4) {
        float4 t = *(const float4*)(vp + c);
        vv[c] = t.x; vv[c + 1] = t.y; vv[c + 2] = t.z; vv[c + 3] = t.w;
    }
    const float* wp = Wft + (size_t)n * 64;
    float f[4];
#pragma unroll
    for (int o = 0; o < 4; o++) {
        float acc = bft[n * 4 + o];
#pragma unroll
        for (int c = 0; c < 16; c++) acc = fmaf(vv[c], wp[o * 16 + c], acc);
        f[o] = acc;
    }
    out[(size_t)b * 8192 + n]        = f[0] - f[1];
    out[(size_t)b * 8192 + 4096 + n] = f[2] - f[3];
}

// ---------------------------------------------------------------------------

static inline int smem_bytes(int S, int BB) {
    int HH = (S / 2) * (S / 2);
    int pad = (HH < 32) ? HH : 0;
    int CHB = 16 * S * S + pad;
    return (4 * 1024 + 64 + BB * CHB) * 4;
}

extern "C" void kernel_launch(void* const* d_in, const int* in_sizes, int n_in,
                              void* d_out, int out_size)
{
    (void)n_in; (void)out_size;
    const float* x  = (const float*)d_in[0];
    const float* W0 = (const float*)d_in[1];
    const float* b0 = (const float*)d_in[2];
    const float *W1, *b1, *W2, *b2, *W3, *b3, *W4, *b4, *W5, *b5, *Wft, *bft;
    if (in_sizes[3] == 262144) {
        Wft = (const float*)d_in[3];  bft = (const float*)d_in[4];
        W1 = (const float*)d_in[5];   b1 = (const float*)d_in[6];
        W2 = (const float*)d_in[7];   b2 = (const float*)d_in[8];
        W3 = (const float*)d_in[9];   b3 = (const float*)d_in[10];
        W4 = (const float*)d_in[11];  b4 = (const float*)d_in[12];
        W5 = (const float*)d_in[13];  b5 = (const float*)d_in[14];
    } else {
        W1 = (const float*)d_in[3];   b1 = (const float*)d_in[4];
        W2 = (const float*)d_in[5];   b2 = (const float*)d_in[6];
        W3 = (const float*)d_in[7];   b3 = (const float*)d_in[8];
        W4 = (const float*)d_in[9];   b4 = (const float*)d_in[10];
        W5 = (const float*)d_in[11];  b5 = (const float*)d_in[12];
        Wft = (const float*)d_in[13]; bft = (const float*)d_in[14];
    }
    float* out = (float*)d_out;

    float *bufA, *bufB;
    cudaGetSymbolAddress((void**)&bufA, g_bufA);
    cudaGetSymbolAddress((void**)&bufB, g_bufB);

    const int s1 = smem_bytes(32, 1);
    const int s2 = smem_bytes(16, 2);
    const int s3 = smem_bytes(8, 8);
    const int s4 = smem_bytes(4, 32);
    const int s5 = smem_bytes(2, 128);
    cudaFuncSetAttribute(k_layer<32, 1, 2>,   cudaFuncAttributeMaxDynamicSharedMemorySize, s1);
    cudaFuncSetAttribute(k_layer<16, 2, 4>,   cudaFuncAttributeMaxDynamicSharedMemorySize, s2);
    cudaFuncSetAttribute(k_layer<8, 8, 8>,    cudaFuncAttributeMaxDynamicSharedMemorySize, s3);
    cudaFuncSetAttribute(k_layer<4, 32, 16>,  cudaFuncAttributeMaxDynamicSharedMemorySize, s4);
    cudaFuncSetAttribute(k_layer<2, 128, 32>, cudaFuncAttributeMaxDynamicSharedMemorySize, s5);

    k_layer0<<<dim3(4, BATCH), 256>>>(x, W0, b0, bufA);
    k_layer<32, 1, 2><<<dim3(4, 256), 256, s1>>>(bufA, W1, b1, bufB);
    k_layer<16, 2, 4><<<dim3(16, 128), 256, s2>>>(bufB, W2, b2, bufA);
    k_layer<8, 8, 8><<<dim3(64, 32), 256, s3>>>(bufA, W3, b3, bufB);
    k_layer<4, 32, 16><<<dim3(256, 8), 256, s4>>>(bufB, W4, b4, bufA);
    k_layer<2, 128, 32><<<dim3(1024, 2), 256, s5>>>(bufA, W5, b5, bufB);
    k_ft<<<dim3(16, BATCH), 256>>>(bufB, Wft, bft, out);
}